// round 14
// baseline (speedup 1.0000x reference)
#include <cuda_runtime.h>
#include <cuda_bf16.h>
#include <cooperative_groups.h>
#include <math.h>

namespace cg = cooperative_groups;

#define Nn   20000
#define Ee   5000
#define NNZf 160000
#define D    128
#define EPSf 1e-10f
#define ALPHAf 0.2f

#define ECAP 96    // slots per edge segment (Binom mean 32, sd 5.7 -> ~11 sd margin)
#define NCAP 64    // slots per node segment (mean 8, sd 2.8)

#define COOP_BLOCKS 296   // 2 blocks/SM on 148 SMs -> guaranteed co-residency

// chunk counts per phase
#define ECHUNKS  (Ee / 8)                 // 625
#define NLCHUNKS ((Nn * 4 + 255) / 256)   // 313
#define GCHUNKS  ((Nn + 255) / 256)       // 79
#define OCHUNKS  (Nn / 8)                 // 2500

// PDL: allow next kernel in stream to launch early; wait for predecessor data.
#define PDL_TRIGGER() asm volatile("griddepcontrol.launch_dependents;" ::: "memory")
#define PDL_WAIT()    asm volatile("griddepcontrol.wait;" ::: "memory")

// ---------------- device scratch (static globals; no allocation) ----------------
// Per-call accumulators are self-resetting: zero at load; last consumers re-zero.
static __device__ float4 g_node4[Nn];          // (dv, s1x, s2x, pad) packed per node
static __device__ float g_Xp[Nn * D];          // X_proj
static __device__ float g_edge[Ee * D];        // edge correction (edge_feats - G)
static __device__ float g_s1[Nn];
static __device__ float g_s2[Ee];
static __device__ float2 g_tu[Ee];             // (E2[c].a1, E2[c].a2)
static __device__ float g_Zd[Nn];              // sum expm1(cell) over unique present cells
static __device__ float g_G[D];                // sum_i (1/Z_i) * X_proj[i]
static __device__ int   g_cntC[Ee], g_cntR[Nn];
static __device__ int   g_prC[Ee * ECAP];      // row id per col slot
static __device__ float g_pvC[Ee * ECAP];      // val per col slot
static __device__ int   g_pcR[Nn * NCAP];      // col id per row slot
static __device__ float g_pvR[Nn * NCAP];      // val per row slot
static __device__ int   g_cntS[Ee * ECAP];     // dup count per slot (0 = duplicate slot)
static __device__ float g_w[Ee * ECAP];        // delta per col slot (0 for duplicates)

// ---------------- phase bodies (shared by fused + standalone kernels) ----------

__device__ __forceinline__ void edgeLight_body(int bi) {
    const int wl = threadIdx.x >> 5, lane = threadIdx.x & 31;
    const int c = bi * 8 + wl;
    int L = g_cntC[c]; if (L > ECAP) L = ECAP;
    float de = 0.f, ts = 0.f, us = 0.f;
    for (int i = lane; i < L; i += 32) {
        int r = g_prC[c * ECAP + i];
        float v = g_pvC[c * ECAP + i];
        float4 nv = g_node4[r];
        float sv = v * rsqrtf(nv.x + EPSf);
        de += v;
        ts += sv * nv.y;
        us += sv * nv.z;
    }
    #pragma unroll
    for (int off = 16; off; off >>= 1) {
        de += __shfl_xor_sync(0xffffffffu, de, off);
        ts += __shfl_xor_sync(0xffffffffu, ts, off);
        us += __shfl_xor_sync(0xffffffffu, us, off);
    }
    if (lane == 0) {
        float dei = 1.0f / (de + EPSf);
        g_tu[c] = make_float2(ts * dei, us * dei);
    }
}

__device__ __forceinline__ void nodeLight_body(int bi) {
    int t = bi * 256 + threadIdx.x;
    int r = t >> 2;
    int sub = t & 3;
    if (r >= Nn) return;
    int L = g_cntR[r]; if (L > NCAP) L = NCAP;
    float s = 0.f, q = 0.f;
    for (int i = sub; i < L; i += 4) {
        int c = g_pcR[r * NCAP + i];
        float v = g_pvR[r * NCAP + i];
        float2 tu = g_tu[c];
        s += v * tu.x;
        q += v * tu.y;
    }
    s += __shfl_xor_sync(0xffffffffu, s, 1);
    s += __shfl_xor_sync(0xffffffffu, s, 2);
    q += __shfl_xor_sync(0xffffffffu, q, 1);
    q += __shfl_xor_sync(0xffffffffu, q, 2);
    if (sub == 0) {
        float4 nv = g_node4[r];
        float dvi = rsqrtf(nv.x + EPSf);
        g_s1[r] = nv.y + dvi * s;
        if (r < Ee) g_s2[r] = nv.z + dvi * q;
    }
}

__device__ __forceinline__ void Z_body(int bi) {
    if (bi == 0 && threadIdx.x < D) g_G[threadIdx.x] = 0.f;
    const int wl = threadIdx.x >> 5, lane = threadIdx.x & 31;
    const int c = bi * 8 + wl;
    int L = g_cntC[c]; if (L > ECAP) L = ECAP;
    float s2c = g_s2[c];
    for (int i = lane; i < L; i += 32) {
        int cnt = g_cntS[c * ECAP + i];
        float delta = 0.f;
        if (cnt > 0) {
            int r = g_prC[c * ECAP + i];
            float sv = g_s1[r] + s2c;
            sv = (sv > 0.f) ? sv : ALPHAf * sv;
            delta = expm1f((float)cnt * sv);
            if (delta != 0.f) atomicAdd(&g_Zd[r], delta);
        }
        g_w[c * ECAP + i] = delta;
    }
}

__device__ __forceinline__ void G_body(int bi) {
    const int wl = threadIdx.x >> 5, lane = threadIdx.x & 31;
    const int base = bi * 256 + wl * 32;
    int r = base + lane;
    float b = (r < Nn) ? 1.0f / ((float)Ee + g_Zd[r]) : 0.f;
    const float4* Xp4 = (const float4*)g_Xp;
    float4 acc = make_float4(0.f, 0.f, 0.f, 0.f);
    #pragma unroll 4
    for (int j = 0; j < 32; j++) {
        int rr = base + j;
        if (rr < Nn) {
            float bj = __shfl_sync(0xffffffffu, b, j);
            float4 xv = Xp4[rr * 32 + lane];
            acc.x += bj*xv.x; acc.y += bj*xv.y; acc.z += bj*xv.z; acc.w += bj*xv.w;
        }
    }
    atomicAdd(&g_G[lane*4 + 0], acc.x);
    atomicAdd(&g_G[lane*4 + 1], acc.y);
    atomicAdd(&g_G[lane*4 + 2], acc.z);
    atomicAdd(&g_G[lane*4 + 3], acc.w);
}

__device__ __forceinline__ void edgeFeat_body(int bi, int sr[8][ECAP], float sw[8][ECAP]) {
    const int wl = threadIdx.x >> 5, lane = threadIdx.x & 31;
    const int c = bi * 8 + wl;
    int L = g_cntC[c]; if (L > ECAP) L = ECAP;
    for (int i = lane; i < L; i += 32) {
        int r = g_prC[c * ECAP + i];
        sr[wl][i] = r;
        sw[wl][i] = g_w[c * ECAP + i] / ((float)Ee + g_Zd[r]);
    }
    __syncwarp();
    const float4* Xp4 = (const float4*)g_Xp;
    float4 acc = make_float4(0.f, 0.f, 0.f, 0.f);
    int i = 0;
    for (; i + 4 <= L; i += 4) {
        int   r0 = sr[wl][i+0], r1 = sr[wl][i+1], r2 = sr[wl][i+2], r3 = sr[wl][i+3];
        float s0 = sw[wl][i+0], s1 = sw[wl][i+1], s2 = sw[wl][i+2], s3 = sw[wl][i+3];
        float4 a0 = Xp4[r0*32+lane], a1 = Xp4[r1*32+lane];
        float4 a2 = Xp4[r2*32+lane], a3 = Xp4[r3*32+lane];
        acc.x += s0*a0.x + s1*a1.x + s2*a2.x + s3*a3.x;
        acc.y += s0*a0.y + s1*a1.y + s2*a2.y + s3*a3.y;
        acc.z += s0*a0.z + s1*a1.z + s2*a2.z + s3*a3.z;
        acc.w += s0*a0.w + s1*a1.w + s2*a2.w + s3*a3.w;
    }
    for (; i < L; i++) {
        float s0 = sw[wl][i]; float4 a0 = Xp4[sr[wl][i]*32+lane];
        acc.x += s0*a0.x; acc.y += s0*a0.y; acc.z += s0*a0.z; acc.w += s0*a0.w;
    }
    __syncwarp();
    ((float4*)g_edge)[c*32 + lane] = acc;
}

__device__ __forceinline__ void outFeat_body(int bi, const float* __restrict__ bias,
                                             float* __restrict__ out,
                                             int scI[8][NCAP], float scV[8][NCAP]) {
    const int wl = threadIdx.x >> 5, lane = threadIdx.x & 31;
    const int r = bi * 8 + wl;
    int L = g_cntR[r]; if (L > NCAP) L = NCAP;
    for (int i = lane; i < L; i += 32) {
        scI[wl][i] = g_pcR[r * NCAP + i];
        scV[wl][i] = g_pvR[r * NCAP + i];
    }
    __syncwarp();
    const float4* E4 = (const float4*)g_edge;
    float dvr = g_node4[r].x;
    float4 gv = ((const float4*)g_G)[lane];
    float4 bv = ((const float4*)bias)[lane];
    float4 acc = make_float4(bv.x + dvr*gv.x, bv.y + dvr*gv.y,
                             bv.z + dvr*gv.z, bv.w + dvr*gv.w);
    int i = 0;
    for (; i + 4 <= L; i += 4) {
        int   c0 = scI[wl][i+0], c1 = scI[wl][i+1], c2 = scI[wl][i+2], c3 = scI[wl][i+3];
        float s0 = scV[wl][i+0], s1 = scV[wl][i+1], s2 = scV[wl][i+2], s3 = scV[wl][i+3];
        float4 a0 = E4[c0*32+lane], a1 = E4[c1*32+lane];
        float4 a2 = E4[c2*32+lane], a3 = E4[c3*32+lane];
        acc.x += s0*a0.x + s1*a1.x + s2*a2.x + s3*a3.x;
        acc.y += s0*a0.y + s1*a1.y + s2*a2.y + s3*a3.y;
        acc.z += s0*a0.z + s1*a1.z + s2*a2.z + s3*a3.z;
        acc.w += s0*a0.w + s1*a1.w + s2*a2.w + s3*a3.w;
    }
    for (; i < L; i++) {
        float s0 = scV[wl][i]; float4 a0 = E4[scI[wl][i]*32+lane];
        acc.x += s0*a0.x; acc.y += s0*a0.y; acc.z += s0*a0.z; acc.w += s0*a0.w;
    }
    __syncwarp();
    ((float4*)out)[r*32 + lane] = acc;
    if (lane == 0) {
        g_node4[r] = make_float4(0.f, 0.f, 0.f, 0.f);
        g_Zd[r] = 0.f; g_cntR[r] = 0;
        if (r < Ee) g_cntC[r] = 0;
    }
}

// ---------------- pre-phase kernels ----------------

__global__ void k_build(const int* __restrict__ rows, const int* __restrict__ cols,
                        const float* __restrict__ vals) {
    PDL_TRIGGER();
    int k = blockIdx.x * blockDim.x + threadIdx.x;
    if (k >= NNZf) return;
    int r = rows[k], c = cols[k];
    float v = vals[k];
    atomicAdd(((float*)g_node4) + 4 * r, v);
    int rc = atomicAdd(&g_cntC[c], 1);
    int rr = atomicAdd(&g_cntR[r], 1);
    if (rc < ECAP) { g_prC[c * ECAP + rc] = r; g_pvC[c * ECAP + rc] = v; }
    if (rr < NCAP) { g_pcR[r * NCAP + rr] = c; g_pvR[r * NCAP + rr] = v; }
}

__global__ void k_dedupScan() {
    PDL_TRIGGER();
    PDL_WAIT();
    const int wl = threadIdx.x >> 5, lane = threadIdx.x & 31;
    const int c = blockIdx.x * 8 + wl;
    __shared__ int sr[8][ECAP];
    int L = g_cntC[c]; if (L > ECAP) L = ECAP;
    for (int i = lane; i < L; i += 32)
        sr[wl][i] = g_prC[c * ECAP + i];
    __syncwarp();
    for (int i = lane; i < L; i += 32) {
        int r = sr[wl][i];
        bool first = true;
        int cnt = 0;
        for (int j = 0; j < L; j++) {
            if (sr[wl][j] == r) {
                if (j < i) { first = false; break; }
                cnt++;
            }
        }
        g_cntS[c * ECAP + i] = first ? cnt : 0;
    }
}

__global__ void k_proj(const float* __restrict__ x, const float* __restrict__ W,
                       const float* __restrict__ a) {
    __shared__ float Xs[8][132];
    __shared__ float Ws[8][64];
    const int bm = blockIdx.x * 128, bn = blockIdx.y * 64;
    const int tid = threadIdx.x;
    const int tm = (tid >> 4) * 8;
    const int tn = (tid & 15) * 4;
    const int lr = tid >> 1;
    const int lk = (tid & 1) * 4;
    const int wk = tid >> 4;
    float acc[8][4] = {};
    for (int k0 = 0; k0 < D; k0 += 8) {
        int gr = bm + lr;
        float4 xv = make_float4(0.f, 0.f, 0.f, 0.f);
        if (gr < Nn) xv = *(const float4*)(x + (size_t)gr * D + k0 + lk);
        Xs[lk + 0][lr] = xv.x; Xs[lk + 1][lr] = xv.y;
        Xs[lk + 2][lr] = xv.z; Xs[lk + 3][lr] = xv.w;
        if (wk < 8)
            *(float4*)&Ws[wk][tn] = *(const float4*)(W + (size_t)(k0 + wk) * D + bn + tn);
        __syncthreads();
        #pragma unroll
        for (int k = 0; k < 8; k++) {
            float4 a0 = *(const float4*)&Xs[k][tm];
            float4 a1 = *(const float4*)&Xs[k][tm + 4];
            float4 b  = *(const float4*)&Ws[k][tn];
            acc[0][0] += a0.x*b.x; acc[0][1] += a0.x*b.y; acc[0][2] += a0.x*b.z; acc[0][3] += a0.x*b.w;
            acc[1][0] += a0.y*b.x; acc[1][1] += a0.y*b.y; acc[1][2] += a0.y*b.z; acc[1][3] += a0.y*b.w;
            acc[2][0] += a0.z*b.x; acc[2][1] += a0.z*b.y; acc[2][2] += a0.z*b.z; acc[2][3] += a0.z*b.w;
            acc[3][0] += a0.w*b.x; acc[3][1] += a0.w*b.y; acc[3][2] += a0.w*b.z; acc[3][3] += a0.w*b.w;
            acc[4][0] += a1.x*b.x; acc[4][1] += a1.x*b.y; acc[4][2] += a1.x*b.z; acc[4][3] += a1.x*b.w;
            acc[5][0] += a1.y*b.x; acc[5][1] += a1.y*b.y; acc[5][2] += a1.y*b.z; acc[5][3] += a1.y*b.w;
            acc[6][0] += a1.z*b.x; acc[6][1] += a1.z*b.y; acc[6][2] += a1.z*b.z; acc[6][3] += a1.z*b.w;
            acc[7][0] += a1.w*b.x; acc[7][1] += a1.w*b.y; acc[7][2] += a1.w*b.z; acc[7][3] += a1.w*b.w;
        }
        __syncthreads();
    }
    #pragma unroll
    for (int i = 0; i < 8; i++) {
        int r = bm + tm + i;
        if (r < Nn)
            *(float4*)(g_Xp + (size_t)r * D + bn + tn) =
                make_float4(acc[i][0], acc[i][1], acc[i][2], acc[i][3]);
    }
    float4 a1v = *(const float4*)(a + bn + tn);
    float4 a2v = *(const float4*)(a + D + bn + tn);
    #pragma unroll
    for (int i = 0; i < 8; i++) {
        float p = acc[i][0]*a1v.x + acc[i][1]*a1v.y + acc[i][2]*a1v.z + acc[i][3]*a1v.w;
        float q = acc[i][0]*a2v.x + acc[i][1]*a2v.y + acc[i][2]*a2v.z + acc[i][3]*a2v.w;
        #pragma unroll
        for (int off = 1; off < 16; off <<= 1) {
            p += __shfl_xor_sync(0xffffffffu, p, off);
            q += __shfl_xor_sync(0xffffffffu, q, off);
        }
        if ((tid & 15) == 0) {
            int r = bm + tm + i;
            if (r < Nn) {
                atomicAdd(((float*)g_node4) + 4 * r + 1, p);
                atomicAdd(((float*)g_node4) + 4 * r + 2, q);
            }
        }
    }
}

// ---------------- fused cooperative kernel (post-join pipeline) ----------------

__global__ void k_fused(const float* __restrict__ bias, float* __restrict__ out) {
    cg::grid_group grid = cg::this_grid();
    __shared__ int   shI[8][ECAP];
    __shared__ float shF[8][ECAP];
    const int nb = gridDim.x;

    for (int bi = blockIdx.x; bi < ECHUNKS; bi += nb) edgeLight_body(bi);
    grid.sync();
    for (int bi = blockIdx.x; bi < NLCHUNKS; bi += nb) nodeLight_body(bi);
    grid.sync();
    for (int bi = blockIdx.x; bi < ECHUNKS; bi += nb) Z_body(bi);
    grid.sync();
    for (int bi = blockIdx.x; bi < ECHUNKS; bi += nb) edgeFeat_body(bi, shI, shF);
    for (int bi = blockIdx.x; bi < GCHUNKS; bi += nb) G_body(bi);
    grid.sync();
    for (int bi = blockIdx.x; bi < OCHUNKS; bi += nb)
        outFeat_body(bi, bias, out, (int(*)[NCAP])shI, (float(*)[NCAP])shF);
}

// ---------------- standalone fallback kernels ----------------

__global__ void k_edgeLight() { PDL_TRIGGER(); PDL_WAIT(); edgeLight_body(blockIdx.x); }
__global__ void k_nodeLight() { PDL_TRIGGER(); PDL_WAIT(); nodeLight_body(blockIdx.x); }
__global__ void k_Z()         { PDL_TRIGGER(); PDL_WAIT(); Z_body(blockIdx.x); }
__global__ void k_G()         { PDL_TRIGGER(); PDL_WAIT(); G_body(blockIdx.x); }
__global__ void k_edgeFeat() {
    PDL_TRIGGER(); PDL_WAIT();
    __shared__ int   sr[8][ECAP];
    __shared__ float sw[8][ECAP];
    edgeFeat_body(blockIdx.x, sr, sw);
}
__global__ void k_outFeat(const float* __restrict__ bias, float* __restrict__ out) {
    PDL_WAIT();
    __shared__ int   scI[8][NCAP];
    __shared__ float scV[8][NCAP];
    outFeat_body(blockIdx.x, bias, out, scI, scV);
}

// ---------------- host launcher ----------------

static bool launchPDL0(void (*kern)(), dim3 g, dim3 b, cudaStream_t st) {
    cudaLaunchConfig_t cfg = {};
    cfg.gridDim = g; cfg.blockDim = b; cfg.stream = st;
    cudaLaunchAttribute at;
    at.id = cudaLaunchAttributeProgrammaticStreamSerialization;
    at.val.programmaticStreamSerializationAllowed = 1;
    cfg.attrs = &at; cfg.numAttrs = 1;
    if (cudaLaunchKernelEx(&cfg, kern) != cudaSuccess) {
        kern<<<g, b, 0, st>>>();
    }
    return true;
}

extern "C" void kernel_launch(void* const* d_in, const int* in_sizes, int n_in,
                              void* d_out, int out_size) {
    const float* x    = (const float*)d_in[0];
    const int*   rows = (const int*)d_in[1];
    const int*   cols = (const int*)d_in[2];
    const float* vals = (const float*)d_in[3];
    const float* W    = (const float*)d_in[4];
    const float* a    = (const float*)d_in[5];
    const float* bias = (const float*)d_in[6];
    float* out = (float*)d_out;
    (void)in_sizes; (void)n_in; (void)out_size;

    dim3 gProj((Nn + 127) / 128, 2);

    cudaStream_t s2 = 0;
    cudaEvent_t eRoot = 0, eProj = 0;
    bool fork = (cudaStreamCreate(&s2) == cudaSuccess);
    if (fork) {
        if (cudaEventCreateWithFlags(&eRoot, cudaEventDisableTiming) != cudaSuccess ||
            cudaEventCreateWithFlags(&eProj, cudaEventDisableTiming) != cudaSuccess) {
            if (eRoot) cudaEventDestroy(eRoot);
            if (eProj) cudaEventDestroy(eProj);
            cudaStreamDestroy(s2);
            fork = false;
        }
    }

    cudaStream_t mainS = 0;
    if (fork) {
        cudaEventRecord(eRoot, mainS);
        cudaStreamWaitEvent(s2, eRoot, 0);
        k_proj<<<gProj, 256, 0, s2>>>(x, W, a);          // independent branch
        cudaEventRecord(eProj, s2);
        k_build<<<(NNZf + 255) / 256, 256, 0, mainS>>>(rows, cols, vals);
        launchPDL0(k_dedupScan, dim3(ECHUNKS), dim3(256), mainS); // concurrent w/ proj
        cudaStreamWaitEvent(mainS, eProj, 0);            // join: fused needs s1x + dv
    } else {
        k_build<<<(NNZf + 255) / 256, 256>>>(rows, cols, vals);
        k_dedupScan<<<ECHUNKS, 256>>>();
        k_proj<<<gProj, 256>>>(x, W, a);
    }

    // try the fused cooperative kernel; fall back to the separate-kernel chain
    {
        cudaLaunchConfig_t cfg = {};
        cfg.gridDim = dim3(COOP_BLOCKS);
        cfg.blockDim = dim3(256);
        cfg.stream = mainS;
        cudaLaunchAttribute at;
        at.id = cudaLaunchAttributeCooperative;
        at.val.cooperative = 1;
        cfg.attrs = &at; cfg.numAttrs = 1;
        cudaError_t err = cudaLaunchKernelEx(&cfg, k_fused, bias, out);
        if (err != cudaSuccess) {
            (void)cudaGetLastError();  // clear
            launchPDL0(k_edgeLight, dim3(ECHUNKS), dim3(256), mainS);
            launchPDL0(k_nodeLight, dim3(NLCHUNKS), dim3(256), mainS);
            launchPDL0(k_Z, dim3(ECHUNKS), dim3(256), mainS);
            launchPDL0(k_G, dim3(GCHUNKS), dim3(256), mainS);
            launchPDL0(k_edgeFeat, dim3(ECHUNKS), dim3(256), mainS);
            {
                cudaLaunchConfig_t c2 = {};
                c2.gridDim = dim3(OCHUNKS); c2.blockDim = dim3(256); c2.stream = mainS;
                cudaLaunchAttribute a2;
                a2.id = cudaLaunchAttributeProgrammaticStreamSerialization;
                a2.val.programmaticStreamSerializationAllowed = 1;
                c2.attrs = &a2; c2.numAttrs = 1;
                if (cudaLaunchKernelEx(&c2, k_outFeat, bias, out) != cudaSuccess)
                    k_outFeat<<<OCHUNKS, 256, 0, mainS>>>(bias, out);
            }
        }
    }

    if (fork) {
        cudaEventDestroy(eRoot);
        cudaEventDestroy(eProj);
        cudaStreamDestroy(s2);
    }
}

// round 15
// speedup vs baseline: 1.5658x; 1.5658x over previous
#include <cuda_runtime.h>
#include <cuda_bf16.h>
#include <math.h>

#define Nn   20000
#define Ee   5000
#define NNZf 160000
#define D    128
#define EPSf 1e-10f
#define ALPHAf 0.2f

#define ECAP 96    // slots per edge segment (Binom mean 32, sd 5.7 -> ~11 sd margin)
#define NCAP 64    // slots per node segment (mean 8, sd 2.8)

#define ECHUNKS  (Ee / 8)                 // 625
#define NLCHUNKS ((Nn * 4 + 255) / 256)   // 313
#define GCHUNKS  ((Nn + 255) / 256)       // 79
#define OCHUNKS  (Nn / 8)                 // 2500

// PDL: allow next kernel in stream to launch early; wait for predecessor data.
#define PDL_TRIGGER() asm volatile("griddepcontrol.launch_dependents;" ::: "memory")
#define PDL_WAIT()    asm volatile("griddepcontrol.wait;" ::: "memory")

// ---------------- device scratch (static globals; no allocation) ----------------
// Per-call accumulators are self-resetting: zero at load; last consumers re-zero.
static __device__ float4 g_node4[Nn];          // (dv, s1x, s2x, pad) packed per node
static __device__ float g_Xp[Nn * D];          // X_proj
static __device__ float g_edge[Ee * D];        // edge correction (edge_feats - G)
static __device__ float g_s1[Nn];
static __device__ float g_s2[Ee];
static __device__ float2 g_tu[Ee];             // (E2[c].a1, E2[c].a2)
static __device__ float g_Zd[Nn];              // sum expm1(cell) over unique present cells
static __device__ float g_G[D];                // sum_i (1/Z_i) * X_proj[i]
static __device__ int   g_cntC[Ee], g_cntR[Nn];
static __device__ int   g_prC[Ee * ECAP];      // row id per col slot
static __device__ float g_pvC[Ee * ECAP];      // val per col slot
static __device__ int   g_pcR[Nn * NCAP];      // col id per row slot
static __device__ float g_pvR[Nn * NCAP];      // val per row slot
static __device__ int   g_cntS[Ee * ECAP];     // dup count per slot (0 = duplicate slot)
static __device__ float g_w[Ee * ECAP];        // delta per col slot (0 for duplicates)

// ---------------- kernels ----------------

// buckets store (r,v)/(c,v) directly; dv accumulates into g_node4[r].x
__global__ void k_build(const int* __restrict__ rows, const int* __restrict__ cols,
                        const float* __restrict__ vals) {
    PDL_TRIGGER();
    int k = blockIdx.x * blockDim.x + threadIdx.x;
    if (k >= NNZf) return;
    int r = rows[k], c = cols[k];
    float v = vals[k];
    atomicAdd(((float*)g_node4) + 4 * r, v);
    int rc = atomicAdd(&g_cntC[c], 1);
    int rr = atomicAdd(&g_cntR[r], 1);
    if (rc < ECAP) { g_prC[c * ECAP + rc] = r; g_pvC[c * ECAP + rc] = v; }
    if (rr < NCAP) { g_pcR[r * NCAP + rr] = c; g_pvR[r * NCAP + rr] = v; }
}

// O(L^2) duplicate scan per edge (needs only buckets -> concurrent with proj)
__global__ void k_dedupScan() {
    PDL_TRIGGER();
    PDL_WAIT();
    const int wl = threadIdx.x >> 5, lane = threadIdx.x & 31;
    const int c = blockIdx.x * 8 + wl;
    __shared__ int sr[8][ECAP];
    int L = g_cntC[c]; if (L > ECAP) L = ECAP;
    for (int i = lane; i < L; i += 32)
        sr[wl][i] = g_prC[c * ECAP + i];
    __syncwarp();
    for (int i = lane; i < L; i += 32) {
        int r = sr[wl][i];
        bool first = true;
        int cnt = 0;
        for (int j = 0; j < L; j++) {
            if (sr[wl][j] == r) {
                if (j < i) { first = false; break; }
                cnt++;
            }
        }
        g_cntS[c * ECAP + i] = first ? cnt : 0;
    }
}

// X_proj = x @ W (128x64 tile, BK=8, 8x4/thread) + epilogue dots into g_node4.y/.z
__global__ void k_proj(const float* __restrict__ x, const float* __restrict__ W,
                       const float* __restrict__ a) {
    __shared__ float Xs[8][132];
    __shared__ float Ws[8][64];
    const int bm = blockIdx.x * 128, bn = blockIdx.y * 64;
    const int tid = threadIdx.x;
    const int tm = (tid >> 4) * 8;
    const int tn = (tid & 15) * 4;
    const int lr = tid >> 1;
    const int lk = (tid & 1) * 4;
    const int wk = tid >> 4;
    float acc[8][4] = {};
    for (int k0 = 0; k0 < D; k0 += 8) {
        int gr = bm + lr;
        float4 xv = make_float4(0.f, 0.f, 0.f, 0.f);
        if (gr < Nn) xv = *(const float4*)(x + (size_t)gr * D + k0 + lk);
        Xs[lk + 0][lr] = xv.x; Xs[lk + 1][lr] = xv.y;
        Xs[lk + 2][lr] = xv.z; Xs[lk + 3][lr] = xv.w;
        if (wk < 8)
            *(float4*)&Ws[wk][tn] = *(const float4*)(W + (size_t)(k0 + wk) * D + bn + tn);
        __syncthreads();
        #pragma unroll
        for (int k = 0; k < 8; k++) {
            float4 a0 = *(const float4*)&Xs[k][tm];
            float4 a1 = *(const float4*)&Xs[k][tm + 4];
            float4 b  = *(const float4*)&Ws[k][tn];
            acc[0][0] += a0.x*b.x; acc[0][1] += a0.x*b.y; acc[0][2] += a0.x*b.z; acc[0][3] += a0.x*b.w;
            acc[1][0] += a0.y*b.x; acc[1][1] += a0.y*b.y; acc[1][2] += a0.y*b.z; acc[1][3] += a0.y*b.w;
            acc[2][0] += a0.z*b.x; acc[2][1] += a0.z*b.y; acc[2][2] += a0.z*b.z; acc[2][3] += a0.z*b.w;
            acc[3][0] += a0.w*b.x; acc[3][1] += a0.w*b.y; acc[3][2] += a0.w*b.z; acc[3][3] += a0.w*b.w;
            acc[4][0] += a1.x*b.x; acc[4][1] += a1.x*b.y; acc[4][2] += a1.x*b.z; acc[4][3] += a1.x*b.w;
            acc[5][0] += a1.y*b.x; acc[5][1] += a1.y*b.y; acc[5][2] += a1.y*b.z; acc[5][3] += a1.y*b.w;
            acc[6][0] += a1.z*b.x; acc[6][1] += a1.z*b.y; acc[6][2] += a1.z*b.z; acc[6][3] += a1.z*b.w;
            acc[7][0] += a1.w*b.x; acc[7][1] += a1.w*b.y; acc[7][2] += a1.w*b.z; acc[7][3] += a1.w*b.w;
        }
        __syncthreads();
    }
    #pragma unroll
    for (int i = 0; i < 8; i++) {
        int r = bm + tm + i;
        if (r < Nn)
            *(float4*)(g_Xp + (size_t)r * D + bn + tn) =
                make_float4(acc[i][0], acc[i][1], acc[i][2], acc[i][3]);
    }
    float4 a1v = *(const float4*)(a + bn + tn);
    float4 a2v = *(const float4*)(a + D + bn + tn);
    #pragma unroll
    for (int i = 0; i < 8; i++) {
        float p = acc[i][0]*a1v.x + acc[i][1]*a1v.y + acc[i][2]*a1v.z + acc[i][3]*a1v.w;
        float q = acc[i][0]*a2v.x + acc[i][1]*a2v.y + acc[i][2]*a2v.z + acc[i][3]*a2v.w;
        #pragma unroll
        for (int off = 1; off < 16; off <<= 1) {
            p += __shfl_xor_sync(0xffffffffu, p, off);
            q += __shfl_xor_sync(0xffffffffu, q, off);
        }
        if ((tid & 15) == 0) {
            int r = bm + tm + i;
            if (r < Nn) {
                atomicAdd(((float*)g_node4) + 4 * r + 1, p);
                atomicAdd(((float*)g_node4) + 4 * r + 2, q);
            }
        }
    }
}

// warp per edge: t[c]=E2[c].a1, u[c]=E2[c].a2 — single packed node load per slot
__global__ void k_edgeLight() {
    PDL_TRIGGER();
    PDL_WAIT();
    const int wl = threadIdx.x >> 5, lane = threadIdx.x & 31;
    const int c = blockIdx.x * 8 + wl;
    int L = g_cntC[c]; if (L > ECAP) L = ECAP;
    float de = 0.f, ts = 0.f, us = 0.f;
    for (int i = lane; i < L; i += 32) {
        int r = g_prC[c * ECAP + i];
        float v = g_pvC[c * ECAP + i];
        float4 nv = g_node4[r];
        float sv = v * rsqrtf(nv.x + EPSf);
        de += v;
        ts += sv * nv.y;
        us += sv * nv.z;
    }
    #pragma unroll
    for (int off = 16; off; off >>= 1) {
        de += __shfl_xor_sync(0xffffffffu, de, off);
        ts += __shfl_xor_sync(0xffffffffu, ts, off);
        us += __shfl_xor_sync(0xffffffffu, us, off);
    }
    if (lane == 0) {
        float dei = 1.0f / (de + EPSf);
        g_tu[c] = make_float2(ts * dei, us * dei);
    }
}

// 4 lanes per node: s1[r] = s1x + dv_inv * sum v*t[c]; s2 likewise
__global__ void k_nodeLight() {
    PDL_TRIGGER();
    PDL_WAIT();
    int t = blockIdx.x * blockDim.x + threadIdx.x;
    int r = t >> 2;
    int sub = t & 3;
    if (r >= Nn) return;
    int L = g_cntR[r]; if (L > NCAP) L = NCAP;
    float s = 0.f, q = 0.f;
    for (int i = sub; i < L; i += 4) {
        int c = g_pcR[r * NCAP + i];
        float v = g_pvR[r * NCAP + i];
        float2 tu = g_tu[c];
        s += v * tu.x;
        q += v * tu.y;
    }
    s += __shfl_xor_sync(0xffffffffu, s, 1);
    s += __shfl_xor_sync(0xffffffffu, s, 2);
    q += __shfl_xor_sync(0xffffffffu, q, 1);
    q += __shfl_xor_sync(0xffffffffu, q, 2);
    if (sub == 0) {
        float4 nv = g_node4[r];
        float dvi = rsqrtf(nv.x + EPSf);
        g_s1[r] = nv.y + dvi * s;
        if (r < Ee) g_s2[r] = nv.z + dvi * q;
    }
}

// warp per edge: delta = expm1(cnt*lrelu(s1+s2)) for first slots; accumulate Zd.
// Block 0 re-zeroes g_G (edgeFeatG is PDL-ordered after this kernel).
__global__ void k_Z() {
    PDL_TRIGGER();
    PDL_WAIT();
    if (blockIdx.x == 0 && threadIdx.x < D) g_G[threadIdx.x] = 0.f;
    const int wl = threadIdx.x >> 5, lane = threadIdx.x & 31;
    const int c = blockIdx.x * 8 + wl;
    int L = g_cntC[c]; if (L > ECAP) L = ECAP;
    float s2c = g_s2[c];
    for (int i = lane; i < L; i += 32) {
        int cnt = g_cntS[c * ECAP + i];
        float delta = 0.f;
        if (cnt > 0) {
            int r = g_prC[c * ECAP + i];
            float sv = g_s1[r] + s2c;
            sv = (sv > 0.f) ? sv : ALPHAf * sv;
            delta = expm1f((float)cnt * sv);
            if (delta != 0.f) atomicAdd(&g_Zd[r], delta);
        }
        g_w[c * ECAP + i] = delta;
    }
}

// merged: blocks [0,ECHUNKS) do edgeFeat; blocks [ECHUNKS,ECHUNKS+GCHUNKS) do G.
// Both depend only on Zd/w/Xp (post-Z) and write disjoint outputs.
__global__ void k_edgeFeatG() {
    PDL_TRIGGER();
    PDL_WAIT();
    const int wl = threadIdx.x >> 5, lane = threadIdx.x & 31;
    if (blockIdx.x >= ECHUNKS) {
        // ---- G part: G[d] = sum_i (1/(E+Zd[i])) * Xp[i][d]
        const int base = (blockIdx.x - ECHUNKS) * 256 + wl * 32;
        int r = base + lane;
        float b = (r < Nn) ? 1.0f / ((float)Ee + g_Zd[r]) : 0.f;
        const float4* Xp4 = (const float4*)g_Xp;
        float4 acc = make_float4(0.f, 0.f, 0.f, 0.f);
        #pragma unroll 4
        for (int j = 0; j < 32; j++) {
            int rr = base + j;
            if (rr < Nn) {
                float bj = __shfl_sync(0xffffffffu, b, j);
                float4 xv = Xp4[rr * 32 + lane];
                acc.x += bj*xv.x; acc.y += bj*xv.y; acc.z += bj*xv.z; acc.w += bj*xv.w;
            }
        }
        atomicAdd(&g_G[lane*4 + 0], acc.x);
        atomicAdd(&g_G[lane*4 + 1], acc.y);
        atomicAdd(&g_G[lane*4 + 2], acc.z);
        atomicAdd(&g_G[lane*4 + 3], acc.w);
        return;
    }
    // ---- edgeFeat part: corr[c] = sum (delta/(E+Zd[r])) * Xp[r]
    const int c = blockIdx.x * 8 + wl;
    __shared__ int   sr[8][ECAP];
    __shared__ float sw[8][ECAP];
    int L = g_cntC[c]; if (L > ECAP) L = ECAP;
    for (int i = lane; i < L; i += 32) {
        int r = g_prC[c * ECAP + i];
        sr[wl][i] = r;
        sw[wl][i] = g_w[c * ECAP + i] / ((float)Ee + g_Zd[r]);
    }
    __syncwarp();
    const float4* Xp4 = (const float4*)g_Xp;
    float4 acc = make_float4(0.f, 0.f, 0.f, 0.f);
    int i = 0;
    for (; i + 4 <= L; i += 4) {
        int   r0 = sr[wl][i+0], r1 = sr[wl][i+1], r2 = sr[wl][i+2], r3 = sr[wl][i+3];
        float s0 = sw[wl][i+0], s1 = sw[wl][i+1], s2 = sw[wl][i+2], s3 = sw[wl][i+3];
        float4 a0 = Xp4[r0*32+lane], a1 = Xp4[r1*32+lane];
        float4 a2 = Xp4[r2*32+lane], a3 = Xp4[r3*32+lane];
        acc.x += s0*a0.x + s1*a1.x + s2*a2.x + s3*a3.x;
        acc.y += s0*a0.y + s1*a1.y + s2*a2.y + s3*a3.y;
        acc.z += s0*a0.z + s1*a1.z + s2*a2.z + s3*a3.z;
        acc.w += s0*a0.w + s1*a1.w + s2*a2.w + s3*a3.w;
    }
    for (; i < L; i++) {
        float s0 = sw[wl][i]; float4 a0 = Xp4[sr[wl][i]*32+lane];
        acc.x += s0*a0.x; acc.y += s0*a0.y; acc.z += s0*a0.z; acc.w += s0*a0.w;
    }
    ((float4*)g_edge)[c*32 + lane] = acc;
}

// warp per node: out[r] = bias + dv[r]*G + sum v*corr[c]; then self-reset state
__global__ void k_outFeat(const float* __restrict__ bias, float* __restrict__ out) {
    PDL_WAIT();
    const int wl = threadIdx.x >> 5, lane = threadIdx.x & 31;
    const int r = blockIdx.x * 8 + wl;
    __shared__ int   scI[8][NCAP];
    __shared__ float scV[8][NCAP];
    int L = g_cntR[r]; if (L > NCAP) L = NCAP;
    for (int i = lane; i < L; i += 32) {
        scI[wl][i] = g_pcR[r * NCAP + i];
        scV[wl][i] = g_pvR[r * NCAP + i];
    }
    __syncwarp();
    const float4* E4 = (const float4*)g_edge;
    float dvr = g_node4[r].x;
    float4 gv = ((const float4*)g_G)[lane];
    float4 bv = ((const float4*)bias)[lane];
    float4 acc = make_float4(bv.x + dvr*gv.x, bv.y + dvr*gv.y,
                             bv.z + dvr*gv.z, bv.w + dvr*gv.w);
    int i = 0;
    for (; i + 4 <= L; i += 4) {
        int   c0 = scI[wl][i+0], c1 = scI[wl][i+1], c2 = scI[wl][i+2], c3 = scI[wl][i+3];
        float s0 = scV[wl][i+0], s1 = scV[wl][i+1], s2 = scV[wl][i+2], s3 = scV[wl][i+3];
        float4 a0 = E4[c0*32+lane], a1 = E4[c1*32+lane];
        float4 a2 = E4[c2*32+lane], a3 = E4[c3*32+lane];
        acc.x += s0*a0.x + s1*a1.x + s2*a2.x + s3*a3.x;
        acc.y += s0*a0.y + s1*a1.y + s2*a2.y + s3*a3.y;
        acc.z += s0*a0.z + s1*a1.z + s2*a2.z + s3*a3.z;
        acc.w += s0*a0.w + s1*a1.w + s2*a2.w + s3*a3.w;
    }
    for (; i < L; i++) {
        float s0 = scV[wl][i]; float4 a0 = E4[scI[wl][i]*32+lane];
        acc.x += s0*a0.x; acc.y += s0*a0.y; acc.z += s0*a0.z; acc.w += s0*a0.w;
    }
    ((float4*)out)[r*32 + lane] = acc;
    if (lane == 0) {
        g_node4[r] = make_float4(0.f, 0.f, 0.f, 0.f);
        g_Zd[r] = 0.f; g_cntR[r] = 0;
        if (r < Ee) g_cntC[r] = 0;
    }
}

// ---------------- host launcher ----------------

static void launchPDL0(void (*kern)(), dim3 g, dim3 b, cudaStream_t st) {
    cudaLaunchConfig_t cfg = {};
    cfg.gridDim = g; cfg.blockDim = b; cfg.stream = st;
    cudaLaunchAttribute at;
    at.id = cudaLaunchAttributeProgrammaticStreamSerialization;
    at.val.programmaticStreamSerializationAllowed = 1;
    cfg.attrs = &at; cfg.numAttrs = 1;
    if (cudaLaunchKernelEx(&cfg, kern) != cudaSuccess)
        kern<<<g, b, 0, st>>>();
}

extern "C" void kernel_launch(void* const* d_in, const int* in_sizes, int n_in,
                              void* d_out, int out_size) {
    const float* x    = (const float*)d_in[0];
    const int*   rows = (const int*)d_in[1];
    const int*   cols = (const int*)d_in[2];
    const float* vals = (const float*)d_in[3];
    const float* W    = (const float*)d_in[4];
    const float* a    = (const float*)d_in[5];
    const float* bias = (const float*)d_in[6];
    float* out = (float*)d_out;
    (void)in_sizes; (void)n_in; (void)out_size;

    dim3 gProj((Nn + 127) / 128, 2);

    cudaStream_t s2 = 0;
    cudaEvent_t eRoot = 0, eProj = 0;
    bool fork = (cudaStreamCreate(&s2) == cudaSuccess);
    if (fork) {
        if (cudaEventCreateWithFlags(&eRoot, cudaEventDisableTiming) != cudaSuccess ||
            cudaEventCreateWithFlags(&eProj, cudaEventDisableTiming) != cudaSuccess) {
            if (eRoot) cudaEventDestroy(eRoot);
            if (eProj) cudaEventDestroy(eProj);
            cudaStreamDestroy(s2);
            fork = false;
        }
    }

    if (fork) {
        cudaEventRecord(eRoot, 0);
        cudaStreamWaitEvent(s2, eRoot, 0);
        k_proj<<<gProj, 256, 0, s2>>>(x, W, a);        // independent branch
        cudaEventRecord(eProj, s2);

        k_build<<<(NNZf + 255) / 256, 256>>>(rows, cols, vals);
        launchPDL0(k_dedupScan, dim3(ECHUNKS), dim3(256), 0);  // concurrent w/ proj
        cudaStreamWaitEvent(0, eProj, 0);              // join (edgeLight needs s1x+dv)

        launchPDL0(k_edgeLight, dim3(ECHUNKS), dim3(256), 0);
        launchPDL0(k_nodeLight, dim3(NLCHUNKS), dim3(256), 0);
        launchPDL0(k_Z, dim3(ECHUNKS), dim3(256), 0);
        launchPDL0(k_edgeFeatG, dim3(ECHUNKS + GCHUNKS), dim3(256), 0);
        {
            cudaLaunchConfig_t c2 = {};
            c2.gridDim = dim3(OCHUNKS); c2.blockDim = dim3(256); c2.stream = 0;
            cudaLaunchAttribute a2;
            a2.id = cudaLaunchAttributeProgrammaticStreamSerialization;
            a2.val.programmaticStreamSerializationAllowed = 1;
            c2.attrs = &a2; c2.numAttrs = 1;
            if (cudaLaunchKernelEx(&c2, k_outFeat, bias, out) != cudaSuccess)
                k_outFeat<<<OCHUNKS, 256>>>(bias, out);
        }

        cudaEventDestroy(eRoot);
        cudaEventDestroy(eProj);
        cudaStreamDestroy(s2);
    } else {
        k_build<<<(NNZf + 255) / 256, 256>>>(rows, cols, vals);
        k_dedupScan<<<ECHUNKS, 256>>>();
        k_proj<<<gProj, 256>>>(x, W, a);
        k_edgeLight<<<ECHUNKS, 256>>>();
        k_nodeLight<<<NLCHUNKS, 256>>>();
        k_Z<<<ECHUNKS, 256>>>();
        k_edgeFeatG<<<ECHUNKS + GCHUNKS, 256>>>();
        k_outFeat<<<OCHUNKS, 256>>>(bias, out);
    }
}

// round 16
// speedup vs baseline: 1.5740x; 1.0053x over previous
#include <cuda_runtime.h>
#include <cuda_bf16.h>
#include <math.h>

#define Nn   20000
#define Ee   5000
#define NNZf 160000
#define D    128
#define EPSf 1e-10f
#define ALPHAf 0.2f

#define ECAP 96    // slots per edge segment (Binom mean 32, sd 5.7 -> ~11 sd margin)
#define NCAP 64    // slots per node segment (mean 8, sd 2.8)

#define ECHUNKS  (Ee / 8)                 // 625
#define NLCHUNKS ((Nn * 4 + 255) / 256)   // 313
#define GCHUNKS  ((Nn + 255) / 256)       // 79
#define OCHUNKS  (Nn / 8)                 // 2500

// PDL: allow next kernel in stream to launch early; wait for predecessor data.
#define PDL_TRIGGER() asm volatile("griddepcontrol.launch_dependents;" ::: "memory")
#define PDL_WAIT()    asm volatile("griddepcontrol.wait;" ::: "memory")

// ---------------- device scratch (static globals; no allocation) ----------------
// Per-call accumulators are self-resetting: zero at load; last consumers re-zero.
static __device__ float4 g_node4[Nn];          // (dv, s1x, s2x, pad) packed per node
static __device__ float g_Xp[Nn * D];          // X_proj
static __device__ float g_edge[Ee * D];        // edge correction (edge_feats - G)
static __device__ float g_s1[Nn];
static __device__ float g_s2[Ee];
static __device__ float2 g_tu[Ee];             // (E2[c].a1, E2[c].a2)
static __device__ float g_Zd[Nn];              // sum expm1(cell) over unique present cells
static __device__ float g_G[D];                // sum_i (1/Z_i) * X_proj[i]
static __device__ int   g_cntC[Ee], g_cntR[Nn];
static __device__ int2  g_pC[Ee * ECAP];       // (row id, val bits) per col slot — one LDG.64
static __device__ int2  g_pR[Nn * NCAP];       // (col id, val bits) per row slot
static __device__ int   g_cntS[Ee * ECAP];     // dup count per slot (0 = duplicate slot)
static __device__ float g_w[Ee * ECAP];        // delta per col slot (0 for duplicates)

// ---------------- kernels ----------------

// buckets store packed (idx,val) directly; dv accumulates into g_node4[r].x
__global__ void k_build(const int* __restrict__ rows, const int* __restrict__ cols,
                        const float* __restrict__ vals) {
    PDL_TRIGGER();
    int k = blockIdx.x * blockDim.x + threadIdx.x;
    if (k >= NNZf) return;
    int r = rows[k], c = cols[k];
    float v = vals[k];
    int vb = __float_as_int(v);
    atomicAdd(((float*)g_node4) + 4 * r, v);
    int rc = atomicAdd(&g_cntC[c], 1);
    int rr = atomicAdd(&g_cntR[r], 1);
    if (rc < ECAP) g_pC[c * ECAP + rc] = make_int2(r, vb);
    if (rr < NCAP) g_pR[r * NCAP + rr] = make_int2(c, vb);
}

// O(L^2) duplicate scan per edge (needs only buckets -> concurrent with proj)
__global__ void k_dedupScan() {
    PDL_TRIGGER();
    PDL_WAIT();
    const int wl = threadIdx.x >> 5, lane = threadIdx.x & 31;
    const int c = blockIdx.x * 8 + wl;
    __shared__ int sr[8][ECAP];
    int L = g_cntC[c]; if (L > ECAP) L = ECAP;
    for (int i = lane; i < L; i += 32)
        sr[wl][i] = g_pC[c * ECAP + i].x;
    __syncwarp();
    for (int i = lane; i < L; i += 32) {
        int r = sr[wl][i];
        bool first = true;
        int cnt = 0;
        for (int j = 0; j < L; j++) {
            if (sr[wl][j] == r) {
                if (j < i) { first = false; break; }
                cnt++;
            }
        }
        g_cntS[c * ECAP + i] = first ? cnt : 0;
    }
}

// X_proj = x @ W (128x64 tile, BK=8, 8x4/thread) + epilogue dots into g_node4.y/.z
__global__ void k_proj(const float* __restrict__ x, const float* __restrict__ W,
                       const float* __restrict__ a) {
    __shared__ float Xs[8][132];
    __shared__ float Ws[8][64];
    const int bm = blockIdx.x * 128, bn = blockIdx.y * 64;
    const int tid = threadIdx.x;
    const int tm = (tid >> 4) * 8;
    const int tn = (tid & 15) * 4;
    const int lr = tid >> 1;
    const int lk = (tid & 1) * 4;
    const int wk = tid >> 4;
    float acc[8][4] = {};
    for (int k0 = 0; k0 < D; k0 += 8) {
        int gr = bm + lr;
        float4 xv = make_float4(0.f, 0.f, 0.f, 0.f);
        if (gr < Nn) xv = *(const float4*)(x + (size_t)gr * D + k0 + lk);
        Xs[lk + 0][lr] = xv.x; Xs[lk + 1][lr] = xv.y;
        Xs[lk + 2][lr] = xv.z; Xs[lk + 3][lr] = xv.w;
        if (wk < 8)
            *(float4*)&Ws[wk][tn] = *(const float4*)(W + (size_t)(k0 + wk) * D + bn + tn);
        __syncthreads();
        #pragma unroll
        for (int k = 0; k < 8; k++) {
            float4 a0 = *(const float4*)&Xs[k][tm];
            float4 a1 = *(const float4*)&Xs[k][tm + 4];
            float4 b  = *(const float4*)&Ws[k][tn];
            acc[0][0] += a0.x*b.x; acc[0][1] += a0.x*b.y; acc[0][2] += a0.x*b.z; acc[0][3] += a0.x*b.w;
            acc[1][0] += a0.y*b.x; acc[1][1] += a0.y*b.y; acc[1][2] += a0.y*b.z; acc[1][3] += a0.y*b.w;
            acc[2][0] += a0.z*b.x; acc[2][1] += a0.z*b.y; acc[2][2] += a0.z*b.z; acc[2][3] += a0.z*b.w;
            acc[3][0] += a0.w*b.x; acc[3][1] += a0.w*b.y; acc[3][2] += a0.w*b.z; acc[3][3] += a0.w*b.w;
            acc[4][0] += a1.x*b.x; acc[4][1] += a1.x*b.y; acc[4][2] += a1.x*b.z; acc[4][3] += a1.x*b.w;
            acc[5][0] += a1.y*b.x; acc[5][1] += a1.y*b.y; acc[5][2] += a1.y*b.z; acc[5][3] += a1.y*b.w;
            acc[6][0] += a1.z*b.x; acc[6][1] += a1.z*b.y; acc[6][2] += a1.z*b.z; acc[6][3] += a1.z*b.w;
            acc[7][0] += a1.w*b.x; acc[7][1] += a1.w*b.y; acc[7][2] += a1.w*b.z; acc[7][3] += a1.w*b.w;
        }
        __syncthreads();
    }
    #pragma unroll
    for (int i = 0; i < 8; i++) {
        int r = bm + tm + i;
        if (r < Nn)
            *(float4*)(g_Xp + (size_t)r * D + bn + tn) =
                make_float4(acc[i][0], acc[i][1], acc[i][2], acc[i][3]);
    }
    float4 a1v = *(const float4*)(a + bn + tn);
    float4 a2v = *(const float4*)(a + D + bn + tn);
    #pragma unroll
    for (int i = 0; i < 8; i++) {
        float p = acc[i][0]*a1v.x + acc[i][1]*a1v.y + acc[i][2]*a1v.z + acc[i][3]*a1v.w;
        float q = acc[i][0]*a2v.x + acc[i][1]*a2v.y + acc[i][2]*a2v.z + acc[i][3]*a2v.w;
        #pragma unroll
        for (int off = 1; off < 16; off <<= 1) {
            p += __shfl_xor_sync(0xffffffffu, p, off);
            q += __shfl_xor_sync(0xffffffffu, q, off);
        }
        if ((tid & 15) == 0) {
            int r = bm + tm + i;
            if (r < Nn) {
                atomicAdd(((float*)g_node4) + 4 * r + 1, p);
                atomicAdd(((float*)g_node4) + 4 * r + 2, q);
            }
        }
    }
}

// warp per edge: t[c]=E2[c].a1, u[c]=E2[c].a2 — one 8B bucket load + one 16B node load
__global__ void k_edgeLight() {
    PDL_TRIGGER();
    PDL_WAIT();
    const int wl = threadIdx.x >> 5, lane = threadIdx.x & 31;
    const int c = blockIdx.x * 8 + wl;
    int L = g_cntC[c]; if (L > ECAP) L = ECAP;
    float de = 0.f, ts = 0.f, us = 0.f;
    for (int i = lane; i < L; i += 32) {
        int2 pv = g_pC[c * ECAP + i];
        int r = pv.x;
        float v = __int_as_float(pv.y);
        float4 nv = g_node4[r];
        float sv = v * rsqrtf(nv.x + EPSf);
        de += v;
        ts += sv * nv.y;
        us += sv * nv.z;
    }
    #pragma unroll
    for (int off = 16; off; off >>= 1) {
        de += __shfl_xor_sync(0xffffffffu, de, off);
        ts += __shfl_xor_sync(0xffffffffu, ts, off);
        us += __shfl_xor_sync(0xffffffffu, us, off);
    }
    if (lane == 0) {
        float dei = 1.0f / (de + EPSf);
        g_tu[c] = make_float2(ts * dei, us * dei);
    }
}

// 4 lanes per node: s1[r] = s1x + dv_inv * sum v*t[c]; s2 likewise
__global__ void k_nodeLight() {
    PDL_TRIGGER();
    PDL_WAIT();
    int t = blockIdx.x * blockDim.x + threadIdx.x;
    int r = t >> 2;
    int sub = t & 3;
    if (r >= Nn) return;
    int L = g_cntR[r]; if (L > NCAP) L = NCAP;
    float s = 0.f, q = 0.f;
    for (int i = sub; i < L; i += 4) {
        int2 pv = g_pR[r * NCAP + i];
        float v = __int_as_float(pv.y);
        float2 tu = g_tu[pv.x];
        s += v * tu.x;
        q += v * tu.y;
    }
    s += __shfl_xor_sync(0xffffffffu, s, 1);
    s += __shfl_xor_sync(0xffffffffu, s, 2);
    q += __shfl_xor_sync(0xffffffffu, q, 1);
    q += __shfl_xor_sync(0xffffffffu, q, 2);
    if (sub == 0) {
        float4 nv = g_node4[r];
        float dvi = rsqrtf(nv.x + EPSf);
        g_s1[r] = nv.y + dvi * s;
        if (r < Ee) g_s2[r] = nv.z + dvi * q;
    }
}

// warp per edge: delta = expm1(cnt*lrelu(s1+s2)) for first slots; accumulate Zd.
// Block 0 re-zeroes g_G (edgeFeatG is PDL-ordered after this kernel).
__global__ void k_Z() {
    PDL_TRIGGER();
    PDL_WAIT();
    if (blockIdx.x == 0 && threadIdx.x < D) g_G[threadIdx.x] = 0.f;
    const int wl = threadIdx.x >> 5, lane = threadIdx.x & 31;
    const int c = blockIdx.x * 8 + wl;
    int L = g_cntC[c]; if (L > ECAP) L = ECAP;
    float s2c = g_s2[c];
    for (int i = lane; i < L; i += 32) {
        int cnt = g_cntS[c * ECAP + i];
        float delta = 0.f;
        if (cnt > 0) {
            int r = g_pC[c * ECAP + i].x;
            float sv = g_s1[r] + s2c;
            sv = (sv > 0.f) ? sv : ALPHAf * sv;
            delta = expm1f((float)cnt * sv);
            if (delta != 0.f) atomicAdd(&g_Zd[r], delta);
        }
        g_w[c * ECAP + i] = delta;
    }
}

// merged: blocks [0,ECHUNKS) do edgeFeat; blocks [ECHUNKS,ECHUNKS+GCHUNKS) do G.
__global__ void k_edgeFeatG() {
    PDL_TRIGGER();
    PDL_WAIT();
    const int wl = threadIdx.x >> 5, lane = threadIdx.x & 31;
    if (blockIdx.x >= ECHUNKS) {
        // ---- G part: G[d] = sum_i (1/(E+Zd[i])) * Xp[i][d]
        const int base = (blockIdx.x - ECHUNKS) * 256 + wl * 32;
        int r = base + lane;
        float b = (r < Nn) ? 1.0f / ((float)Ee + g_Zd[r]) : 0.f;
        const float4* Xp4 = (const float4*)g_Xp;
        float4 acc = make_float4(0.f, 0.f, 0.f, 0.f);
        #pragma unroll 4
        for (int j = 0; j < 32; j++) {
            int rr = base + j;
            if (rr < Nn) {
                float bj = __shfl_sync(0xffffffffu, b, j);
                float4 xv = Xp4[rr * 32 + lane];
                acc.x += bj*xv.x; acc.y += bj*xv.y; acc.z += bj*xv.z; acc.w += bj*xv.w;
            }
        }
        atomicAdd(&g_G[lane*4 + 0], acc.x);
        atomicAdd(&g_G[lane*4 + 1], acc.y);
        atomicAdd(&g_G[lane*4 + 2], acc.z);
        atomicAdd(&g_G[lane*4 + 3], acc.w);
        return;
    }
    // ---- edgeFeat part: corr[c] = sum (delta/(E+Zd[r])) * Xp[r]
    const int c = blockIdx.x * 8 + wl;
    __shared__ int   sr[8][ECAP];
    __shared__ float sw[8][ECAP];
    int L = g_cntC[c]; if (L > ECAP) L = ECAP;
    for (int i = lane; i < L; i += 32) {
        int r = g_pC[c * ECAP + i].x;
        sr[wl][i] = r;
        sw[wl][i] = g_w[c * ECAP + i] / ((float)Ee + g_Zd[r]);
    }
    __syncwarp();
    const float4* Xp4 = (const float4*)g_Xp;
    float4 acc = make_float4(0.f, 0.f, 0.f, 0.f);
    int i = 0;
    for (; i + 4 <= L; i += 4) {
        int   r0 = sr[wl][i+0], r1 = sr[wl][i+1], r2 = sr[wl][i+2], r3 = sr[wl][i+3];
        float s0 = sw[wl][i+0], s1 = sw[wl][i+1], s2 = sw[wl][i+2], s3 = sw[wl][i+3];
        float4 a0 = Xp4[r0*32+lane], a1 = Xp4[r1*32+lane];
        float4 a2 = Xp4[r2*32+lane], a3 = Xp4[r3*32+lane];
        acc.x += s0*a0.x + s1*a1.x + s2*a2.x + s3*a3.x;
        acc.y += s0*a0.y + s1*a1.y + s2*a2.y + s3*a3.y;
        acc.z += s0*a0.z + s1*a1.z + s2*a2.z + s3*a3.z;
        acc.w += s0*a0.w + s1*a1.w + s2*a2.w + s3*a3.w;
    }
    for (; i < L; i++) {
        float s0 = sw[wl][i]; float4 a0 = Xp4[sr[wl][i]*32+lane];
        acc.x += s0*a0.x; acc.y += s0*a0.y; acc.z += s0*a0.z; acc.w += s0*a0.w;
    }
    ((float4*)g_edge)[c*32 + lane] = acc;
}

// warp per node: out[r] = bias + dv[r]*G + sum v*corr[c]; then self-reset state
__global__ void k_outFeat(const float* __restrict__ bias, float* __restrict__ out) {
    PDL_WAIT();
    const int wl = threadIdx.x >> 5, lane = threadIdx.x & 31;
    const int r = blockIdx.x * 8 + wl;
    __shared__ int   scI[8][NCAP];
    __shared__ float scV[8][NCAP];
    int L = g_cntR[r]; if (L > NCAP) L = NCAP;
    for (int i = lane; i < L; i += 32) {
        int2 pv = g_pR[r * NCAP + i];
        scI[wl][i] = pv.x;
        scV[wl][i] = __int_as_float(pv.y);
    }
    __syncwarp();
    const float4* E4 = (const float4*)g_edge;
    float dvr = g_node4[r].x;
    float4 gv = ((const float4*)g_G)[lane];
    float4 bv = ((const float4*)bias)[lane];
    float4 acc = make_float4(bv.x + dvr*gv.x, bv.y + dvr*gv.y,
                             bv.z + dvr*gv.z, bv.w + dvr*gv.w);
    int i = 0;
    for (; i + 4 <= L; i += 4) {
        int   c0 = scI[wl][i+0], c1 = scI[wl][i+1], c2 = scI[wl][i+2], c3 = scI[wl][i+3];
        float s0 = scV[wl][i+0], s1 = scV[wl][i+1], s2 = scV[wl][i+2], s3 = scV[wl][i+3];
        float4 a0 = E4[c0*32+lane], a1 = E4[c1*32+lane];
        float4 a2 = E4[c2*32+lane], a3 = E4[c3*32+lane];
        acc.x += s0*a0.x + s1*a1.x + s2*a2.x + s3*a3.x;
        acc.y += s0*a0.y + s1*a1.y + s2*a2.y + s3*a3.y;
        acc.z += s0*a0.z + s1*a1.z + s2*a2.z + s3*a3.z;
        acc.w += s0*a0.w + s1*a1.w + s2*a2.w + s3*a3.w;
    }
    for (; i < L; i++) {
        float s0 = scV[wl][i]; float4 a0 = E4[scI[wl][i]*32+lane];
        acc.x += s0*a0.x; acc.y += s0*a0.y; acc.z += s0*a0.z; acc.w += s0*a0.w;
    }
    ((float4*)out)[r*32 + lane] = acc;
    if (lane == 0) {
        g_node4[r] = make_float4(0.f, 0.f, 0.f, 0.f);
        g_Zd[r] = 0.f; g_cntR[r] = 0;
        if (r < Ee) g_cntC[r] = 0;
    }
}

// ---------------- host launcher ----------------

static void launchPDL0(void (*kern)(), dim3 g, dim3 b, cudaStream_t st) {
    cudaLaunchConfig_t cfg = {};
    cfg.gridDim = g; cfg.blockDim = b; cfg.stream = st;
    cudaLaunchAttribute at;
    at.id = cudaLaunchAttributeProgrammaticStreamSerialization;
    at.val.programmaticStreamSerializationAllowed = 1;
    cfg.attrs = &at; cfg.numAttrs = 1;
    if (cudaLaunchKernelEx(&cfg, kern) != cudaSuccess)
        kern<<<g, b, 0, st>>>();
}

extern "C" void kernel_launch(void* const* d_in, const int* in_sizes, int n_in,
                              void* d_out, int out_size) {
    const float* x    = (const float*)d_in[0];
    const int*   rows = (const int*)d_in[1];
    const int*   cols = (const int*)d_in[2];
    const float* vals = (const float*)d_in[3];
    const float* W    = (const float*)d_in[4];
    const float* a    = (const float*)d_in[5];
    const float* bias = (const float*)d_in[6];
    float* out = (float*)d_out;
    (void)in_sizes; (void)n_in; (void)out_size;

    dim3 gProj((Nn + 127) / 128, 2);

    cudaStream_t s2 = 0;
    cudaEvent_t eRoot = 0, eProj = 0;
    bool fork = (cudaStreamCreate(&s2) == cudaSuccess);
    if (fork) {
        if (cudaEventCreateWithFlags(&eRoot, cudaEventDisableTiming) != cudaSuccess ||
            cudaEventCreateWithFlags(&eProj, cudaEventDisableTiming) != cudaSuccess) {
            if (eRoot) cudaEventDestroy(eRoot);
            if (eProj) cudaEventDestroy(eProj);
            cudaStreamDestroy(s2);
            fork = false;
        }
    }

    if (fork) {
        cudaEventRecord(eRoot, 0);
        cudaStreamWaitEvent(s2, eRoot, 0);
        k_proj<<<gProj, 256, 0, s2>>>(x, W, a);        // independent branch
        cudaEventRecord(eProj, s2);

        k_build<<<(NNZf + 255) / 256, 256>>>(rows, cols, vals);
        launchPDL0(k_dedupScan, dim3(ECHUNKS), dim3(256), 0);  // concurrent w/ proj
        cudaStreamWaitEvent(0, eProj, 0);              // join (edgeLight needs s1x+dv)

        launchPDL0(k_edgeLight, dim3(ECHUNKS), dim3(256), 0);
        launchPDL0(k_nodeLight, dim3(NLCHUNKS), dim3(256), 0);
        launchPDL0(k_Z, dim3(ECHUNKS), dim3(256), 0);
        launchPDL0(k_edgeFeatG, dim3(ECHUNKS + GCHUNKS), dim3(256), 0);
        {
            cudaLaunchConfig_t c2 = {};
            c2.gridDim = dim3(OCHUNKS); c2.blockDim = dim3(256); c2.stream = 0;
            cudaLaunchAttribute a2;
            a2.id = cudaLaunchAttributeProgrammaticStreamSerialization;
            a2.val.programmaticStreamSerializationAllowed = 1;
            c2.attrs = &a2; c2.numAttrs = 1;
            if (cudaLaunchKernelEx(&c2, k_outFeat, bias, out) != cudaSuccess)
                k_outFeat<<<OCHUNKS, 256>>>(bias, out);
        }

        cudaEventDestroy(eRoot);
        cudaEventDestroy(eProj);
        cudaStreamDestroy(s2);
    } else {
        k_build<<<(NNZf + 255) / 256, 256>>>(rows, cols, vals);
        k_dedupScan<<<ECHUNKS, 256>>>();
        k_proj<<<gProj, 256>>>(x, W, a);
        k_edgeLight<<<ECHUNKS, 256>>>();
        k_nodeLight<<<NLCHUNKS, 256>>>();
        k_Z<<<ECHUNKS, 256>>>();
        k_edgeFeatG<<<ECHUNKS + GCHUNKS, 256>>>();
        k_outFeat<<<OCHUNKS, 256>>>(bias, out);
    }
}